// round 4
// baseline (speedup 1.0000x reference)
#include <cuda_runtime.h>

#define VOCAB 32000
#define EDIM  1024
#define HDIM  1024
#define NLAY  2
#define BSZ   64
#define TST   64
#define GDIM  4096          // 4*HDIM
#define KS_L  8             // split-K chunks for LSTM GEMMs (chunk = 128)
#define KS_E  8             // split-K chunks for o2emb GEMM (chunk = 128)
#define NB_V  (VOCAB/128)   // 250 score blocks
#define START_TOK 1

// ---------------- scratch (device globals; no allocation allowed) ----------
__device__ float g_h[NLAY][BSZ][HDIM];
__device__ float g_c[NLAY][BSZ][HDIM];
__device__ float g_gates[KS_L][BSZ][GDIM];
__device__ float g_hidp[KS_E][BSZ][EDIM];
__device__ float g_hid[BSZ][EDIM];
__device__ float g_pval[BSZ][NB_V];
__device__ int   g_pidx[BSZ][NB_V];
__device__ int   g_tok[BSZ];

// ---------------- GEMM tile helpers (BM=64, BN=128, BK=32, 128 thr, 8x8) ---
// As stored transposed [k][b] (stride 68), Bs transposed [k][n] (stride 132)
// so the inner product reads are conflict-free float4 LDS.

__device__ __forceinline__ void load_A(float As[32][68], const float* __restrict__ A,
                                       int lda, int kpos) {
  const int tid = threadIdx.x;
#pragma unroll
  for (int p = 0; p < 4; p++) {
    int idx = p * 128 + tid;
    int r = idx >> 3, c4 = idx & 7;
    float4 v = *(const float4*)(A + (size_t)r * lda + kpos + c4 * 4);
    As[c4 * 4 + 0][r] = v.x; As[c4 * 4 + 1][r] = v.y;
    As[c4 * 4 + 2][r] = v.z; As[c4 * 4 + 3][r] = v.w;
  }
}

__device__ __forceinline__ void load_A_gather(float As[32][68], const float* __restrict__ A,
                                              int lda, int kpos, const int* stok) {
  const int tid = threadIdx.x;
#pragma unroll
  for (int p = 0; p < 4; p++) {
    int idx = p * 128 + tid;
    int r = idx >> 3, c4 = idx & 7;
    int row = stok[r];
    float4 v = *(const float4*)(A + (size_t)row * lda + kpos + c4 * 4);
    As[c4 * 4 + 0][r] = v.x; As[c4 * 4 + 1][r] = v.y;
    As[c4 * 4 + 2][r] = v.z; As[c4 * 4 + 3][r] = v.w;
  }
}

__device__ __forceinline__ void load_B(float Bs[32][132], const float* __restrict__ W,
                                       int ldw, int n0, int kpos) {
  const int tid = threadIdx.x;
#pragma unroll
  for (int p = 0; p < 8; p++) {
    int idx = p * 128 + tid;
    int r = idx >> 3, c4 = idx & 7;
    float4 v = *(const float4*)(W + (size_t)(n0 + r) * ldw + kpos + c4 * 4);
    Bs[c4 * 4 + 0][r] = v.x; Bs[c4 * 4 + 1][r] = v.y;
    Bs[c4 * 4 + 2][r] = v.z; Bs[c4 * 4 + 3][r] = v.w;
  }
}

__device__ __forceinline__ void mma32(const float As[32][68], const float Bs[32][132],
                                      float acc[8][8], int ty, int tx) {
#pragma unroll
  for (int k = 0; k < 32; k++) {
    float a[8], b[8];
    *(float4*)(a)     = *(const float4*)(&As[k][ty * 8]);
    *(float4*)(a + 4) = *(const float4*)(&As[k][ty * 8 + 4]);
    *(float4*)(b)     = *(const float4*)(&Bs[k][tx * 8]);
    *(float4*)(b + 4) = *(const float4*)(&Bs[k][tx * 8 + 4]);
#pragma unroll
    for (int i = 0; i < 8; i++)
#pragma unroll
      for (int j = 0; j < 8; j++)
        acc[i][j] = fmaf(a[i], b[j], acc[i][j]);
  }
}

// ---------------- kernels ----------------

__global__ void k_init() {
  int i = blockIdx.x * blockDim.x + threadIdx.x;
  if (i < NLAY * BSZ * HDIM) {
    (&g_h[0][0][0])[i] = 0.f;
    (&g_c[0][0][0])[i] = 0.f;
  }
  if (i < BSZ) g_tok[i] = START_TOK;
}

// gates partial: g_gates[chunk][b][n] = x@w_ih^T + h@w_hh^T over K-chunk
__global__ __launch_bounds__(128) void k_gates(const float* __restrict__ emb,
                                               const float* __restrict__ wih,
                                               const float* __restrict__ whh,
                                               int layer) {
  __shared__ float As[32][68];
  __shared__ float Bs[32][132];
  __shared__ int stok[BSZ];
  const int tid = threadIdx.x;
  if (layer == 0 && tid < BSZ) stok[tid] = g_tok[tid];
  __syncthreads();

  const int n0 = blockIdx.x * 128;
  const int kc = blockIdx.y * (HDIM / KS_L);
  const int ty = tid >> 4, tx = tid & 15;
  float acc[8][8];
#pragma unroll
  for (int i = 0; i < 8; i++)
#pragma unroll
    for (int j = 0; j < 8; j++) acc[i][j] = 0.f;

  const float* xsrc = (layer == 0) ? emb : &g_h[0][0][0];
  const float* hin  = &g_h[layer][0][0];

  for (int kt = 0; kt < HDIM / KS_L; kt += 32) {
    if (layer == 0) load_A_gather(As, emb, EDIM, kc + kt, stok);
    else            load_A(As, xsrc, HDIM, kc + kt);
    load_B(Bs, wih, HDIM, n0, kc + kt);
    __syncthreads();
    mma32(As, Bs, acc, ty, tx);
    __syncthreads();
  }
  for (int kt = 0; kt < HDIM / KS_L; kt += 32) {
    load_A(As, hin, HDIM, kc + kt);
    load_B(Bs, whh, HDIM, n0, kc + kt);
    __syncthreads();
    mma32(As, Bs, acc, ty, tx);
    __syncthreads();
  }

#pragma unroll
  for (int i = 0; i < 8; i++) {
    int b = ty * 8 + i;
    float* dst = &g_gates[blockIdx.y][b][n0 + tx * 8];
    *(float4*)(dst)     = make_float4(acc[i][0], acc[i][1], acc[i][2], acc[i][3]);
    *(float4*)(dst + 4) = make_float4(acc[i][4], acc[i][5], acc[i][6], acc[i][7]);
  }
}

// reduce split-K partials + biases, apply LSTM cell (gate order i,f,g,o)
__global__ void k_act(const float* __restrict__ bih, const float* __restrict__ bhh,
                      int layer) {
  int i = blockIdx.x * blockDim.x + threadIdx.x;
  if (i >= BSZ * HDIM) return;
  int b = i >> 10, hh = i & (HDIM - 1);
  float gi = bih[hh]            + bhh[hh];
  float gf = bih[HDIM + hh]     + bhh[HDIM + hh];
  float gg = bih[2 * HDIM + hh] + bhh[2 * HDIM + hh];
  float go = bih[3 * HDIM + hh] + bhh[3 * HDIM + hh];
#pragma unroll
  for (int c = 0; c < KS_L; c++) {
    gi += g_gates[c][b][hh];
    gf += g_gates[c][b][HDIM + hh];
    gg += g_gates[c][b][2 * HDIM + hh];
    go += g_gates[c][b][3 * HDIM + hh];
  }
  float si = 1.f / (1.f + expf(-gi));
  float sf = 1.f / (1.f + expf(-gf));
  float so = 1.f / (1.f + expf(-go));
  float tg = tanhf(gg);
  float cn = sf * g_c[layer][b][hh] + si * tg;
  float hn = so * tanhf(cn);
  g_c[layer][b][hh] = cn;
  g_h[layer][b][hh] = hn;
}

// o2emb partial GEMM: g_hidp[chunk][b][e] = h_top @ o2emb_w^T over K-chunk
__global__ __launch_bounds__(128) void k_o2emb(const float* __restrict__ w) {
  __shared__ float As[32][68];
  __shared__ float Bs[32][132];
  const int tid = threadIdx.x;
  const int n0 = blockIdx.x * 128;
  const int kc = blockIdx.y * (HDIM / KS_E);
  const int ty = tid >> 4, tx = tid & 15;
  float acc[8][8];
#pragma unroll
  for (int i = 0; i < 8; i++)
#pragma unroll
    for (int j = 0; j < 8; j++) acc[i][j] = 0.f;

  const float* A = &g_h[NLAY - 1][0][0];
  for (int kt = 0; kt < HDIM / KS_E; kt += 32) {
    load_A(As, A, HDIM, kc + kt);
    load_B(Bs, w, HDIM, n0, kc + kt);
    __syncthreads();
    mma32(As, Bs, acc, ty, tx);
    __syncthreads();
  }
#pragma unroll
  for (int i = 0; i < 8; i++) {
    int b = ty * 8 + i;
    float* dst = &g_hidp[blockIdx.y][b][n0 + tx * 8];
    *(float4*)(dst)     = make_float4(acc[i][0], acc[i][1], acc[i][2], acc[i][3]);
    *(float4*)(dst + 4) = make_float4(acc[i][4], acc[i][5], acc[i][6], acc[i][7]);
  }
}

__global__ void k_hidred(const float* __restrict__ o2b) {
  int i = blockIdx.x * blockDim.x + threadIdx.x;
  if (i >= BSZ * EDIM) return;
  int b = i >> 10, e = i & (EDIM - 1);
  float s = o2b[e];
#pragma unroll
  for (int c = 0; c < KS_E; c++) s += g_hidp[c][b][e];
  g_hid[b][e] = fmaxf(s, 0.f);
}

// score GEMM + bias + per-block argmax partials; writes scores to d_out[b][t][v]
__global__ __launch_bounds__(128) void k_score(const float* __restrict__ sw,
                                               const float* __restrict__ sb,
                                               float* __restrict__ out, int t) {
  __shared__ float As[32][68];
  __shared__ float Bs[32][132];
  __shared__ float rv[BSZ][16];
  __shared__ int   ri[BSZ][16];
  const int tid = threadIdx.x;
  const int n0 = blockIdx.x * 128;
  const int ty = tid >> 4, tx = tid & 15;
  float acc[8][8];
#pragma unroll
  for (int i = 0; i < 8; i++)
#pragma unroll
    for (int j = 0; j < 8; j++) acc[i][j] = 0.f;

  for (int kt = 0; kt < EDIM; kt += 32) {
    load_A(As, &g_hid[0][0], EDIM, kt);
    load_B(Bs, sw, EDIM, n0, kt);
    __syncthreads();
    mma32(As, Bs, acc, ty, tx);
    __syncthreads();
  }

  float bias[8];
#pragma unroll
  for (int j = 0; j < 8; j++) bias[j] = sb[n0 + tx * 8 + j];

#pragma unroll
  for (int i = 0; i < 8; i++) {
    int b = ty * 8 + i;
    float v[8];
#pragma unroll
    for (int j = 0; j < 8; j++) v[j] = acc[i][j] + bias[j];
    float* dst = out + ((size_t)b * TST + t) * VOCAB + n0 + tx * 8;
    *(float4*)(dst)     = make_float4(v[0], v[1], v[2], v[3]);
    *(float4*)(dst + 4) = make_float4(v[4], v[5], v[6], v[7]);
    float best = v[0];
    int bidx = n0 + tx * 8;
#pragma unroll
    for (int j = 1; j < 8; j++)
      if (v[j] > best) { best = v[j]; bidx = n0 + tx * 8 + j; }
    rv[b][tx] = best; ri[b][tx] = bidx;
  }
  __syncthreads();
  if (tid < BSZ) {
    float best = rv[tid][0]; int bi = ri[tid][0];
#pragma unroll
    for (int x = 1; x < 16; x++) {
      float v = rv[tid][x]; int ix = ri[tid][x];
      if (v > best || (v == best && ix < bi)) { best = v; bi = ix; }
    }
    g_pval[tid][blockIdx.x] = best;
    g_pidx[tid][blockIdx.x] = bi;
  }
}

// final argmax over the 250 block partials; updates tokens, writes samples
__global__ void k_argmax(float* __restrict__ out, int t, int write_samples) {
  int tid = threadIdx.x;          // 256 threads: 4 per batch row
  int b = tid >> 2, l4 = tid & 3;
  float bv = -3.0e38f; int bi = 0x7fffffff;
  for (int p = l4; p < NB_V; p += 4) {
    float v = g_pval[b][p]; int ix = g_pidx[b][p];
    if (v > bv || (v == bv && ix < bi)) { bv = v; bi = ix; }
  }
#pragma unroll
  for (int off = 2; off >= 1; off >>= 1) {
    float ov = __shfl_down_sync(0xffffffffu, bv, off, 4);
    int   oi = __shfl_down_sync(0xffffffffu, bi, off, 4);
    if (ov > bv || (ov == bv && oi < bi)) { bv = ov; bi = oi; }
  }
  if (l4 == 0) {
    g_tok[b] = bi;
    if (write_samples)
      out[(size_t)BSZ * TST * VOCAB + (size_t)b * TST + t] = (float)bi;
  }
}

// ---------------- host orchestration (graph-capturable) ----------------
extern "C" void kernel_launch(void* const* d_in, const int* in_sizes, int n_in,
                              void* d_out, int out_size) {
  const float* emb = (const float*)d_in[0];
  const float* wih = (const float*)d_in[1];
  const float* whh = (const float*)d_in[2];
  const float* bih = (const float*)d_in[3];
  const float* bhh = (const float*)d_in[4];
  const float* o2w = (const float*)d_in[5];
  const float* o2b = (const float*)d_in[6];
  const float* sw  = (const float*)d_in[7];
  const float* sb  = (const float*)d_in[8];
  float* out = (float*)d_out;
  int wsamp = (out_size >= BSZ * TST * VOCAB + BSZ * TST) ? 1 : 0;

  k_init<<<(NLAY * BSZ * HDIM + 255) / 256, 256>>>();

  for (int t = 0; t < TST; t++) {
    for (int l = 0; l < NLAY; l++) {
      k_gates<<<dim3(GDIM / 128, KS_L), 128>>>(emb,
          wih + (size_t)l * GDIM * HDIM, whh + (size_t)l * GDIM * HDIM, l);
      k_act<<<(BSZ * HDIM + 255) / 256, 256>>>(bih + l * GDIM, bhh + l * GDIM, l);
    }
    k_o2emb<<<dim3(EDIM / 128, KS_E), 128>>>(o2w);
    k_hidred<<<(BSZ * EDIM + 255) / 256, 256>>>(o2b);
    k_score<<<NB_V, 128>>>(sw, sb, out, t);
    k_argmax<<<1, 256>>>(out, t, wsamp);
  }
}

// round 7
// speedup vs baseline: 1.5472x; 1.5472x over previous
#include <cuda_runtime.h>
#include <cuda_bf16.h>
#include <cstdint>

#define VOCAB 32000
#define EDIM  1024
#define HDIM  1024
#define NLAY  2
#define BSZ   64
#define TST   64
#define GDIM  4096
#define NB_V  (VOCAB/128)
#define START_TOK 1

#define RS 72                         /* smem row stride in bf16 (conflict-free) */
#define A_LIMB (64*RS)                /* 4608 bf16 per A limb tile  */
#define B_LIMB (128*RS)               /* 9216 bf16 per B limb tile  */
#define SMEM_SZ ((3*A_LIMB + 3*B_LIMB)*2)   /* 82944 bytes */

// ---------------- device globals (no allocation allowed) -------------------
__device__ __nv_bfloat16 d_wih_s[3][NLAY*GDIM*HDIM];
__device__ __nv_bfloat16 d_whh_s[3][NLAY*GDIM*HDIM];
__device__ __nv_bfloat16 d_o2w_s[3][EDIM*HDIM];
__device__ __nv_bfloat16 d_sw_s[3][VOCAB*EDIM];
__device__ __nv_bfloat16 d_xs[3][64*HDIM];
__device__ __nv_bfloat16 d_hs[NLAY][3][64*HDIM];
__device__ __nv_bfloat16 d_hid_s[3][64*HDIM];
__device__ float g_part[16][BSZ][GDIM];
__device__ float e_part[8][BSZ][EDIM];
__device__ float g_c[NLAY][BSZ][HDIM];
__device__ float g_pval[BSZ][NB_V];
__device__ int   g_pidx[BSZ][NB_V];
__device__ int   g_tok[BSZ];

// bf16 warp MMA: D(16x8,f32) += A(16x16,row) * B(16x8,col)   [sm_80+, plain target]
#define MMA_BF16(d, a, b)                                                     \
  asm volatile("mma.sync.aligned.m16n8k16.row.col.f32.bf16.bf16.f32 "         \
    "{%0,%1,%2,%3},{%4,%5,%6,%7},{%8,%9},{%0,%1,%2,%3};"                      \
    : "+f"((d)[0]), "+f"((d)[1]), "+f"((d)[2]), "+f"((d)[3])                  \
    : "r"((a)[0]), "r"((a)[1]), "r"((a)[2]), "r"((a)[3]),                     \
      "r"((b)[0]), "r"((b)[1]))

// exact fp32 -> 3 bf16 limbs (each subtraction exact; residual ~2^-27)
__device__ __forceinline__ void split3(float x, __nv_bfloat16& b0,
                                       __nv_bfloat16& b1, __nv_bfloat16& b2) {
  b0 = __float2bfloat16(x);
  float r = x - __bfloat162float(b0);
  b1 = __float2bfloat16(r);
  b2 = __float2bfloat16(r - __bfloat162float(b1));
}
__device__ __forceinline__ const __nv_bfloat16* getA(int s, int l) {
  switch (s) { case 0: return d_xs[l]; case 1: return d_hs[0][l];
               case 2: return d_hs[1][l]; default: return d_hid_s[l]; }
}
__device__ __forceinline__ const __nv_bfloat16* getB(int s, int l) {
  switch (s) {
    case 0: return d_wih_s[l];
    case 1: return d_whh_s[l];
    case 2: return d_wih_s[l] + (size_t)GDIM * HDIM;
    case 3: return d_whh_s[l] + (size_t)GDIM * HDIM;
    case 4: return d_o2w_s[l];
    default: return d_sw_s[l];
  }
}

// ---------------- setup kernels ----------------
__global__ void k_init() {
  int i = blockIdx.x * blockDim.x + threadIdx.x;
  if (i < 3 * 64 * HDIM)        (&d_xs[0][0])[i]    = __float2bfloat16(0.f);
  if (i < NLAY * 3 * 64 * HDIM) (&d_hs[0][0][0])[i] = __float2bfloat16(0.f);
  if (i < 3 * 64 * HDIM)        (&d_hid_s[0][0])[i] = __float2bfloat16(0.f);
  if (i < NLAY * BSZ * HDIM)    (&g_c[0][0][0])[i]  = 0.f;
  if (i < BSZ) g_tok[i] = START_TOK;
}

__global__ void k_splitw(const float* __restrict__ src, int which, long long n) {
  __nv_bfloat16 *p0, *p1, *p2;
  switch (which) {
    case 0:  p0 = d_wih_s[0]; p1 = d_wih_s[1]; p2 = d_wih_s[2]; break;
    case 1:  p0 = d_whh_s[0]; p1 = d_whh_s[1]; p2 = d_whh_s[2]; break;
    case 2:  p0 = d_o2w_s[0]; p1 = d_o2w_s[1]; p2 = d_o2w_s[2]; break;
    default: p0 = d_sw_s[0];  p1 = d_sw_s[1];  p2 = d_sw_s[2];  break;
  }
  long long stride = (long long)gridDim.x * blockDim.x;
  for (long long i = (long long)blockIdx.x * blockDim.x + threadIdx.x; i < n; i += stride) {
    __nv_bfloat16 b0, b1, b2;
    split3(src[i], b0, b1, b2);
    p0[i] = b0; p1[i] = b1; p2[i] = b2;
  }
}

__global__ void k_embed(const float* __restrict__ emb) {
  int i = blockIdx.x * blockDim.x + threadIdx.x;
  if (i >= BSZ * EDIM) return;
  int b = i >> 10, e = i & (EDIM - 1);
  __nv_bfloat16 b0, b1, b2;
  split3(emb[(size_t)g_tok[b] * EDIM + e], b0, b1, b2);
  d_xs[0][b * HDIM + e] = b0; d_xs[1][b * HDIM + e] = b1; d_xs[2][b * HDIM + e] = b2;
}

// ---------------- bf16x3 HMMA GEMM (M=64, Ntile=128, 128 thr = 4 warps) ----
// blockIdx.y: split-K slice (and A/B-set phase for fused gates GEMM).
// mode 0: gates partial -> g_part[y]; 1: o2emb partial -> e_part[y];
// mode 2: score fused bias + out store + per-block argmax partial.
__global__ __launch_bounds__(128) void k_mm(int a1, int b1, int a2, int b2,
                                            int cpb, int ysplit, int mode,
                                            const float* __restrict__ bias,
                                            float* __restrict__ out, int t) {
  extern __shared__ __nv_bfloat16 sm[];
  __nv_bfloat16* Asm = sm;                 // limb l at l*A_LIMB
  __nv_bfloat16* Bsm = sm + 3 * A_LIMB;    // limb l at l*B_LIMB
  const int tid = threadIdx.x, wid = tid >> 5, lane = tid & 31;
  const int qr = lane >> 2, qc = lane & 3;
  const int n0 = blockIdx.x * 128;
  const int y = blockIdx.y;
  const int as = (y < ysplit) ? a1 : a2, bs = (y < ysplit) ? b1 : b2;
  const int kbase = ((y < ysplit) ? y : (y - ysplit)) * cpb * 64;

  const __nv_bfloat16* Ap[3]; const __nv_bfloat16* Bp[3];
#pragma unroll
  for (int l = 0; l < 3; l++) { Ap[l] = getA(as, l); Bp[l] = getB(bs, l); }

  float acc[16][4];
#pragma unroll
  for (int i = 0; i < 16; i++)
#pragma unroll
    for (int j = 0; j < 4; j++) acc[i][j] = 0.f;

  for (int ch = 0; ch < cpb; ch++) {
    const int kpos = kbase + ch * 64;
    __syncthreads();                              // protect prior-iter reads
    for (int i = tid; i < 3 * 512; i += 128) {    // A limbs: 64 rows x 64 k
      int l = i >> 9, q = i & 511, row = q >> 3, f8 = q & 7;
      *(float4*)(Asm + l * A_LIMB + row * RS + f8 * 8) =
          *(const float4*)(Ap[l] + (size_t)row * 1024 + kpos + f8 * 8);
    }
    for (int i = tid; i < 3 * 1024; i += 128) {   // B limbs: 128 rows x 64 k
      int l = i >> 10, q = i & 1023, row = q >> 3, f8 = q & 7;
      *(float4*)(Bsm + l * B_LIMB + row * RS + f8 * 8) =
          *(const float4*)(Bp[l] + (size_t)(n0 + row) * 1024 + kpos + f8 * 8);
    }
    __syncthreads();

#pragma unroll
    for (int k16 = 0; k16 < 4; k16++) {
      const __nv_bfloat16* ab = Asm + wid * 16 * RS + k16 * 16;
      uint32_t afr[3][4];
#pragma unroll
      for (int l = 0; l < 3; l++) {
        const __nv_bfloat16* a = ab + l * A_LIMB;
        afr[l][0] = *(const uint32_t*)(a + qr * RS + qc * 2);
        afr[l][1] = *(const uint32_t*)(a + (qr + 8) * RS + qc * 2);
        afr[l][2] = *(const uint32_t*)(a + qr * RS + qc * 2 + 8);
        afr[l][3] = *(const uint32_t*)(a + (qr + 8) * RS + qc * 2 + 8);
      }
#pragma unroll
      for (int n8 = 0; n8 < 16; n8++) {
        const __nv_bfloat16* bb = Bsm + (n8 * 8 + qr) * RS + k16 * 16 + qc * 2;
        uint32_t bfr[3][2];
#pragma unroll
        for (int l = 0; l < 3; l++) {
          bfr[l][0] = *(const uint32_t*)(bb + l * B_LIMB);
          bfr[l][1] = *(const uint32_t*)(bb + l * B_LIMB + 8);
        }
        MMA_BF16(acc[n8], afr[0], bfr[0]);   // b0*c0
        MMA_BF16(acc[n8], afr[0], bfr[1]);   // b0*c1
        MMA_BF16(acc[n8], afr[1], bfr[0]);   // b1*c0
        MMA_BF16(acc[n8], afr[0], bfr[2]);   // b0*c2
        MMA_BF16(acc[n8], afr[1], bfr[1]);   // b1*c1
        MMA_BF16(acc[n8], afr[2], bfr[0]);   // b2*c0
      }
    }
  }

  // epilogue: thread owns rows r0,r1 = wid*16+qr, +8; cols n8*8 + qc*2 (+1)
  const int r0 = wid * 16 + qr, r1 = r0 + 8;
  if (mode == 2) {
    float bv0 = -3.0e38f, bv1 = -3.0e38f; int bi0 = 0, bi1 = 0;
#pragma unroll
    for (int n8 = 0; n8 < 16; n8++) {
      int c = n0 + n8 * 8 + qc * 2;
      float b0 = bias[c], b1 = bias[c + 1];
      float v00 = acc[n8][0] + b0, v01 = acc[n8][1] + b1;
      float v10 = acc[n8][2] + b0, v11 = acc[n8][3] + b1;
      *(float2*)(out + ((size_t)r0 * TST + t) * VOCAB + c) = make_float2(v00, v01);
      *(float2*)(out + ((size_t)r1 * TST + t) * VOCAB + c) = make_float2(v10, v11);
      if (v00 > bv0) { bv0 = v00; bi0 = c; }
      if (v01 > bv0) { bv0 = v01; bi0 = c + 1; }
      if (v10 > bv1) { bv1 = v10; bi1 = c; }
      if (v11 > bv1) { bv1 = v11; bi1 = c + 1; }
    }
#pragma unroll
    for (int m = 1; m <= 2; m <<= 1) {           // reduce over qc group (4 lanes)
      float ov = __shfl_xor_sync(0xffffffffu, bv0, m);
      int   oi = __shfl_xor_sync(0xffffffffu, bi0, m);
      if (ov > bv0 || (ov == bv0 && oi < bi0)) { bv0 = ov; bi0 = oi; }
      ov = __shfl_xor_sync(0xffffffffu, bv1, m);
      oi = __shfl_xor_sync(0xffffffffu, bi1, m);
      if (ov > bv1 || (ov == bv1 && oi < bi1)) { bv1 = ov; bi1 = oi; }
    }
    if (qc == 0) {
      g_pval[r0][blockIdx.x] = bv0; g_pidx[r0][blockIdx.x] = bi0;
      g_pval[r1][blockIdx.x] = bv1; g_pidx[r1][blockIdx.x] = bi1;
    }
  } else {
    float* base = (mode == 0) ? &g_part[y][0][0] : &e_part[y][0][0];
    const int ld = (mode == 0) ? GDIM : EDIM;
#pragma unroll
    for (int n8 = 0; n8 < 16; n8++) {
      int c = n0 + n8 * 8 + qc * 2;
      *(float2*)(base + (size_t)r0 * ld + c) = make_float2(acc[n8][0], acc[n8][1]);
      *(float2*)(base + (size_t)r1 * ld + c) = make_float2(acc[n8][2], acc[n8][3]);
    }
  }
}

// reduce 16 gate partials + biases, apply LSTM cell, emit h limbs + c
__global__ void k_act(const float* __restrict__ bih, const float* __restrict__ bhh,
                      int layer) {
  int i = blockIdx.x * blockDim.x + threadIdx.x;
  if (i >= BSZ * HDIM) return;
  int b = i >> 10, hh = i & (HDIM - 1);
  float gi = bih[hh]            + bhh[hh];
  float gf = bih[HDIM + hh]     + bhh[HDIM + hh];
  float gg = bih[2 * HDIM + hh] + bhh[2 * HDIM + hh];
  float go = bih[3 * HDIM + hh] + bhh[3 * HDIM + hh];
#pragma unroll
  for (int s = 0; s < 16; s++) {
    gi += g_part[s][b][hh];
    gf += g_part[s][b][HDIM + hh];
    gg += g_part[s][b][2 * HDIM + hh];
    go += g_part[s][b][3 * HDIM + hh];
  }
  float si = 1.f / (1.f + expf(-gi));
  float sf = 1.f / (1.f + expf(-gf));
  float so = 1.f / (1.f + expf(-go));
  float cn = sf * g_c[layer][b][hh] + si * tanhf(gg);
  float hn = so * tanhf(cn);
  g_c[layer][b][hh] = cn;
  __nv_bfloat16 h0, h1, h2;
  split3(hn, h0, h1, h2);
  d_hs[layer][0][b * HDIM + hh] = h0;
  d_hs[layer][1][b * HDIM + hh] = h1;
  d_hs[layer][2][b * HDIM + hh] = h2;
}

// reduce 8 o2emb partials + bias, ReLU, emit hid limbs
__global__ void k_hidred(const float* __restrict__ o2b) {
  int i = blockIdx.x * blockDim.x + threadIdx.x;
  if (i >= BSZ * EDIM) return;
  int b = i >> 10, e = i & (EDIM - 1);
  float s = o2b[e];
#pragma unroll
  for (int c = 0; c < 8; c++) s += e_part[c][b][e];
  s = fmaxf(s, 0.f);
  __nv_bfloat16 h0, h1, h2;
  split3(s, h0, h1, h2);
  d_hid_s[0][b * EDIM + e] = h0;
  d_hid_s[1][b * EDIM + e] = h1;
  d_hid_s[2][b * EDIM + e] = h2;
}

// final argmax over 250 block partials; update tokens, write samples
__global__ void k_argmax(float* __restrict__ out, int t, int write_samples) {
  int tid = threadIdx.x;
  int b = tid >> 2, l4 = tid & 3;
  float bv = -3.0e38f; int bi = 0x7fffffff;
  for (int p = l4; p < NB_V; p += 4) {
    float v = g_pval[b][p]; int ix = g_pidx[b][p];
    if (v > bv || (v == bv && ix < bi)) { bv = v; bi = ix; }
  }
#pragma unroll
  for (int off = 2; off >= 1; off >>= 1) {
    float ov = __shfl_down_sync(0xffffffffu, bv, off, 4);
    int   oi = __shfl_down_sync(0xffffffffu, bi, off, 4);
    if (ov > bv || (ov == bv && oi < bi)) { bv = ov; bi = oi; }
  }
  if (l4 == 0) {
    g_tok[b] = bi;
    if (write_samples)
      out[(size_t)BSZ * TST * VOCAB + (size_t)b * TST + t] = (float)bi;
  }
}

// ---------------- host orchestration (graph-capturable) ----------------
extern "C" void kernel_launch(void* const* d_in, const int* in_sizes, int n_in,
                              void* d_out, int out_size) {
  const float* emb = (const float*)d_in[0];
  const float* wih = (const float*)d_in[1];
  const float* whh = (const float*)d_in[2];
  const float* bih = (const float*)d_in[3];
  const float* bhh = (const float*)d_in[4];
  const float* o2w = (const float*)d_in[5];
  const float* o2b = (const float*)d_in[6];
  const float* sw  = (const float*)d_in[7];
  const float* sb  = (const float*)d_in[8];
  float* out = (float*)d_out;
  int wsamp = (out_size >= BSZ * TST * VOCAB + BSZ * TST) ? 1 : 0;

  cudaFuncSetAttribute(k_mm, cudaFuncAttributeMaxDynamicSharedMemorySize, SMEM_SZ);

  k_init<<<1024, 256>>>();
  k_splitw<<<1184, 256>>>(wih, 0, (long long)NLAY * GDIM * HDIM);
  k_splitw<<<1184, 256>>>(whh, 1, (long long)NLAY * GDIM * HDIM);
  k_splitw<<<592, 256>>>(o2w, 2, (long long)EDIM * HDIM);
  k_splitw<<<1184, 256>>>(sw, 3, (long long)VOCAB * EDIM);

  for (int t = 0; t < TST; t++) {
    k_embed<<<256, 256>>>(emb);
    // layer 0: x(=emb limbs)@Wih0 (y<8) + h0@Whh0 (y>=8)
    k_mm<<<dim3(GDIM / 128, 16), 128, SMEM_SZ>>>(0, 0, 1, 1, 2, 8, 0, nullptr, nullptr, 0);
    k_act<<<256, 256>>>(bih, bhh, 0);
    // layer 1: h0@Wih1 + h1@Whh1
    k_mm<<<dim3(GDIM / 128, 16), 128, SMEM_SZ>>>(1, 2, 2, 3, 2, 8, 0, nullptr, nullptr, 0);
    k_act<<<256, 256>>>(bih + GDIM, bhh + GDIM, 1);
    // o2emb: h1 @ o2w
    k_mm<<<dim3(EDIM / 128, 8), 128, SMEM_SZ>>>(2, 4, 2, 4, 2, 8, 1, nullptr, nullptr, 0);
    k_hidred<<<256, 256>>>(o2b);
    // score: hid @ sw  (full K per block, fused bias/out/argmax)
    k_mm<<<dim3(NB_V, 1), 128, SMEM_SZ>>>(3, 5, 3, 5, 16, 1, 2, sb, out, t);
    k_argmax<<<1, 256>>>(out, t, wsamp);
  }
}

// round 8
// speedup vs baseline: 1.5945x; 1.0306x over previous
#include <cuda_runtime.h>
#include <cuda_bf16.h>
#include <cstdint>

#define VOCAB 32000
#define EDIM  1024
#define HDIM  1024
#define NLAY  2
#define BSZ   64
#define TST   64
#define GDIM  4096
#define NB_V  (VOCAB/128)             /* 250 score x-blocks */
#define START_TOK 1

#define RS 72                         /* smem row stride in bf16 */
#define A_LIMB (64*RS)                /* bf16 per A limb tile */
#define B_LIMB (128*RS)               /* bf16 per B limb tile */
#define STAGE_ELE (3*A_LIMB + 3*B_LIMB)      /* 41472 bf16 */
#define SMEM_SZ (2*STAGE_ELE*2)              /* 165888 bytes, 2 stages */

// ---------------- device globals (no allocation allowed) -------------------
__device__ __nv_bfloat16 d_wih_s[3][NLAY*GDIM*HDIM];
__device__ __nv_bfloat16 d_whh_s[3][NLAY*GDIM*HDIM];
__device__ __nv_bfloat16 d_o2w_s[3][EDIM*HDIM];
__device__ __nv_bfloat16 d_sw_s[3][VOCAB*EDIM];
__device__ __nv_bfloat16 d_xs[3][64*HDIM];
__device__ __nv_bfloat16 d_hs[NLAY][3][64*HDIM];
__device__ __nv_bfloat16 d_hid_s[3][64*HDIM];
__device__ float g_part[8][BSZ][GDIM];
__device__ float e_part[8][BSZ][EDIM];
__device__ float g_c[NLAY][BSZ][HDIM];
__device__ float g_pval[BSZ][512];
__device__ int   g_pidx[BSZ][512];
__device__ int   g_tok[BSZ];

// bf16 warp MMA: D(16x8,f32) += A(16x16,row) * B(16x8,col)  [sm_80+, plain]
#define MMA_BF16(d, a, b)                                                     \
  asm volatile("mma.sync.aligned.m16n8k16.row.col.f32.bf16.bf16.f32 "         \
    "{%0,%1,%2,%3},{%4,%5,%6,%7},{%8,%9},{%0,%1,%2,%3};"                      \
    : "+f"((d)[0]), "+f"((d)[1]), "+f"((d)[2]), "+f"((d)[3])                  \
    : "r"((a)[0]), "r"((a)[1]), "r"((a)[2]), "r"((a)[3]),                     \
      "r"((b)[0]), "r"((b)[1]))

#define LDSM_X4(r0,r1,r2,r3, ad)                                              \
  asm volatile("ldmatrix.sync.aligned.m8n8.x4.shared.b16 {%0,%1,%2,%3}, [%4];"\
    : "=r"(r0), "=r"(r1), "=r"(r2), "=r"(r3) : "r"(ad))
#define LDSM_X2(r0,r1, ad)                                                    \
  asm volatile("ldmatrix.sync.aligned.m8n8.x2.shared.b16 {%0,%1}, [%2];"      \
    : "=r"(r0), "=r"(r1) : "r"(ad))

#define CP_A16(dst, src)                                                      \
  asm volatile("cp.async.cg.shared.global [%0], [%1], 16;"                    \
    :: "r"(dst), "l"(src) : "memory")
#define CP_COMMIT() asm volatile("cp.async.commit_group;" ::: "memory")
#define CP_WAIT0()  asm volatile("cp.async.wait_group 0;" ::: "memory")
#define CP_WAIT1()  asm volatile("cp.async.wait_group 1;" ::: "memory")

__device__ __forceinline__ uint32_t smem_u32(const void* p) {
  uint32_t a;
  asm("{ .reg .u64 t; cvta.to.shared.u64 t, %1; cvt.u32.u64 %0, t; }" : "=r"(a) : "l"(p));
  return a;
}
// exact fp32 -> 3 bf16 limbs (subtractions exact; residual ~2^-27)
__device__ __forceinline__ void split3(float x, __nv_bfloat16& b0,
                                       __nv_bfloat16& b1, __nv_bfloat16& b2) {
  b0 = __float2bfloat16(x);
  float r = x - __bfloat162float(b0);
  b1 = __float2bfloat16(r);
  b2 = __float2bfloat16(r - __bfloat162float(b1));
}
__device__ __forceinline__ const __nv_bfloat16* getA(int s, int l) {
  switch (s) { case 0: return d_xs[l]; case 1: return d_hs[0][l];
               case 2: return d_hs[1][l]; default: return d_hid_s[l]; }
}
__device__ __forceinline__ const __nv_bfloat16* getB(int s, int l) {
  switch (s) {
    case 0: return d_wih_s[l];
    case 1: return d_whh_s[l];
    case 2: return d_wih_s[l] + (size_t)GDIM * HDIM;
    case 3: return d_whh_s[l] + (size_t)GDIM * HDIM;
    case 4: return d_o2w_s[l];
    default: return d_sw_s[l];
  }
}

// ---------------- setup kernels ----------------
__global__ void k_init() {
  int i = blockIdx.x * blockDim.x + threadIdx.x;
  if (i < 3 * 64 * HDIM)        (&d_xs[0][0])[i]    = __float2bfloat16(0.f);
  if (i < NLAY * 3 * 64 * HDIM) (&d_hs[0][0][0])[i] = __float2bfloat16(0.f);
  if (i < 3 * 64 * HDIM)        (&d_hid_s[0][0])[i] = __float2bfloat16(0.f);
  if (i < NLAY * BSZ * HDIM)    (&g_c[0][0][0])[i]  = 0.f;
  if (i < BSZ) g_tok[i] = START_TOK;
}

__global__ void k_splitw(const float* __restrict__ src, int which, long long n) {
  __nv_bfloat16 *p0, *p1, *p2;
  switch (which) {
    case 0:  p0 = d_wih_s[0]; p1 = d_wih_s[1]; p2 = d_wih_s[2]; break;
    case 1:  p0 = d_whh_s[0]; p1 = d_whh_s[1]; p2 = d_whh_s[2]; break;
    case 2:  p0 = d_o2w_s[0]; p1 = d_o2w_s[1]; p2 = d_o2w_s[2]; break;
    default: p0 = d_sw_s[0];  p1 = d_sw_s[1];  p2 = d_sw_s[2];  break;
  }
  long long stride = (long long)gridDim.x * blockDim.x;
  for (long long i = (long long)blockIdx.x * blockDim.x + threadIdx.x; i < n; i += stride) {
    __nv_bfloat16 b0, b1, b2;
    split3(src[i], b0, b1, b2);
    p0[i] = b0; p1[i] = b1; p2[i] = b2;
  }
}

__global__ void k_embed(const float* __restrict__ emb) {
  int i = blockIdx.x * blockDim.x + threadIdx.x;
  if (i >= BSZ * EDIM) return;
  int b = i >> 10, e = i & (EDIM - 1);
  __nv_bfloat16 b0, b1, b2;
  split3(emb[(size_t)g_tok[b] * EDIM + e], b0, b1, b2);
  d_xs[0][b * HDIM + e] = b0; d_xs[1][b * HDIM + e] = b1; d_xs[2][b * HDIM + e] = b2;
}

// ---------------- bf16x3 HMMA GEMM, cp.async 2-stage pipeline --------------
// 128 thr = 4 warps; warp (wm=wid>>1 gives M32 slice, wn=wid&1 gives N64 half).
// mode 0: gates partial -> g_part[y]; 1: o2emb partial -> e_part[y];
// mode 2: score fused bias + out store + per-(block,wn) argmax partial.
__global__ __launch_bounds__(128) void k_mm(int a1, int b1, int a2, int b2,
                                            int cpb, int ysplit, int mode,
                                            const float* __restrict__ bias,
                                            float* __restrict__ out, int t) {
  extern __shared__ __nv_bfloat16 sm[];
  const uint32_t sbase = smem_u32(sm);
  const int tid = threadIdx.x, wid = tid >> 5, lane = tid & 31;
  const int qr = lane >> 2, qc = lane & 3;
  const int wm = wid >> 1, wn = wid & 1;
  const int n0 = blockIdx.x * 128;
  const int y = blockIdx.y;
  const int as = (y < ysplit) ? a1 : a2, bs = (y < ysplit) ? b1 : b2;
  const int kbase = ((y < ysplit) ? y : (y - ysplit)) * cpb * 64;

  const __nv_bfloat16* Ap[3]; const __nv_bfloat16* Bp[3];
#pragma unroll
  for (int l = 0; l < 3; l++) { Ap[l] = getA(as, l); Bp[l] = getB(bs, l); }

  // per-lane ldmatrix address pieces
  const int arow = ((lane >> 3) & 1) * 8 + (lane & 7);
  const int akof = ((lane >> 4) & 1) * 8;
  const uint32_t A_pre = (uint32_t)(((wm * 32 + arow) * RS + akof) * 2);
  const int brow = lane & 7;
  const int bkof = ((lane >> 3) & 1) * 8;
  const uint32_t B_pre = (uint32_t)(((wn * 64 + brow) * RS + bkof) * 2);

  float acc[2][8][4];
#pragma unroll
  for (int m = 0; m < 2; m++)
#pragma unroll
    for (int i = 0; i < 8; i++)
#pragma unroll
      for (int j = 0; j < 4; j++) acc[m][i][j] = 0.f;

  // async tile loader: chunk ch -> stage s
  auto issue_load = [&](int s, int ch) {
    const int kpos = kbase + ch * 64;
    const uint32_t st = sbase + (uint32_t)(s * STAGE_ELE * 2);
#pragma unroll 2
    for (int i = tid; i < 3 * 512; i += 128) {     // A limbs: 64 rows x 64 k
      int l = i >> 9, q = i & 511, row = q >> 3, f8 = q & 7;
      CP_A16(st + (uint32_t)((l * A_LIMB + row * RS + f8 * 8) * 2),
             Ap[l] + (size_t)row * 1024 + kpos + f8 * 8);
    }
#pragma unroll 2
    for (int i = tid; i < 3 * 1024; i += 128) {    // B limbs: 128 rows x 64 k
      int l = i >> 10, q = i & 1023, row = q >> 3, f8 = q & 7;
      CP_A16(st + (uint32_t)((3 * A_LIMB + l * B_LIMB + row * RS + f8 * 8) * 2),
             Bp[l] + (size_t)(n0 + row) * 1024 + kpos + f8 * 8);
    }
    CP_COMMIT();
  };

  issue_load(0, 0);
  const int pa[6] = {0, 0, 1, 0, 1, 2}, pb[6] = {0, 1, 0, 2, 1, 0};

  for (int ch = 0; ch < cpb; ch++) {
    const int cur = ch & 1;
    if (ch + 1 < cpb) { issue_load(cur ^ 1, ch + 1); CP_WAIT1(); }
    else              { CP_WAIT0(); }
    __syncthreads();
    const uint32_t sA = sbase + (uint32_t)(cur * STAGE_ELE * 2);
    const uint32_t sB = sA + (uint32_t)(3 * A_LIMB * 2);

#pragma unroll
    for (int k16 = 0; k16 < 4; k16++) {
      uint32_t afr[2][3][4];
      const uint32_t ak = sA + A_pre + k16 * 32;
#pragma unroll
      for (int mt = 0; mt < 2; mt++)
#pragma unroll
        for (int l = 0; l < 3; l++)
          LDSM_X4(afr[mt][l][0], afr[mt][l][1], afr[mt][l][2], afr[mt][l][3],
                  ak + (uint32_t)((l * A_LIMB + mt * 16 * RS) * 2));
      const uint32_t bk = sB + B_pre + k16 * 32;
#pragma unroll
      for (int n8p = 0; n8p < 4; n8p++) {
        uint32_t bfr[2][3][2];
#pragma unroll
        for (int j = 0; j < 2; j++)
#pragma unroll
          for (int l = 0; l < 3; l++)
            LDSM_X2(bfr[j][l][0], bfr[j][l][1],
                    bk + (uint32_t)((l * B_LIMB + (n8p * 2 + j) * 8 * RS) * 2));
#pragma unroll
        for (int p = 0; p < 6; p++)
#pragma unroll
          for (int mt = 0; mt < 2; mt++)
#pragma unroll
            for (int j = 0; j < 2; j++)
              MMA_BF16(acc[mt][n8p * 2 + j], afr[mt][pa[p]], bfr[j][pb[p]]);
      }
    }
    __syncthreads();
  }

  // epilogue: thread owns rows wm*32+mt*16+qr(+8); cols n0+wn*64+n8*8+qc*2(+1)
  if (mode == 2) {
#pragma unroll
    for (int mt = 0; mt < 2; mt++) {
      const int r0 = wm * 32 + mt * 16 + qr, r1 = r0 + 8;
      float bv0 = -3.0e38f, bv1 = -3.0e38f; int bi0 = 0, bi1 = 0;
#pragma unroll
      for (int n8 = 0; n8 < 8; n8++) {
        int c = n0 + wn * 64 + n8 * 8 + qc * 2;
        float b0 = bias[c], b1 = bias[c + 1];
        float v00 = acc[mt][n8][0] + b0, v01 = acc[mt][n8][1] + b1;
        float v10 = acc[mt][n8][2] + b0, v11 = acc[mt][n8][3] + b1;
        *(float2*)(out + ((size_t)r0 * TST + t) * VOCAB + c) = make_float2(v00, v01);
        *(float2*)(out + ((size_t)r1 * TST + t) * VOCAB + c) = make_float2(v10, v11);
        if (v00 > bv0) { bv0 = v00; bi0 = c; }
        if (v01 > bv0) { bv0 = v01; bi0 = c + 1; }
        if (v10 > bv1) { bv1 = v10; bi1 = c; }
        if (v11 > bv1) { bv1 = v11; bi1 = c + 1; }
      }
#pragma unroll
      for (int m = 1; m <= 2; m <<= 1) {    // reduce over qc quad
        float ov = __shfl_xor_sync(0xffffffffu, bv0, m);
        int   oi = __shfl_xor_sync(0xffffffffu, bi0, m);
        if (ov > bv0 || (ov == bv0 && oi < bi0)) { bv0 = ov; bi0 = oi; }
        ov = __shfl_xor_sync(0xffffffffu, bv1, m);
        oi = __shfl_xor_sync(0xffffffffu, bi1, m);
        if (ov > bv1 || (ov == bv1 && oi < bi1)) { bv1 = ov; bi1 = oi; }
      }
      if (qc == 0) {
        g_pval[r0][blockIdx.x * 2 + wn] = bv0; g_pidx[r0][blockIdx.x * 2 + wn] = bi0;
        g_pval[r1][blockIdx.x * 2 + wn] = bv1; g_pidx[r1][blockIdx.x * 2 + wn] = bi1;
      }
    }
  } else {
    float* base = (mode == 0) ? &g_part[y][0][0] : &e_part[y][0][0];
    const int ld = (mode == 0) ? GDIM : EDIM;
#pragma unroll
    for (int mt = 0; mt < 2; mt++) {
      const int r0 = wm * 32 + mt * 16 + qr, r1 = r0 + 8;
#pragma unroll
      for (int n8 = 0; n8 < 8; n8++) {
        int c = n0 + wn * 64 + n8 * 8 + qc * 2;
        *(float2*)(base + (size_t)r0 * ld + c) = make_float2(acc[mt][n8][0], acc[mt][n8][1]);
        *(float2*)(base + (size_t)r1 * ld + c) = make_float2(acc[mt][n8][2], acc[mt][n8][3]);
      }
    }
  }
}

// reduce 8 gate partials + biases, LSTM cell, emit h limbs + c
__global__ void k_act(const float* __restrict__ bih, const float* __restrict__ bhh,
                      int layer) {
  int i = blockIdx.x * blockDim.x + threadIdx.x;
  if (i >= BSZ * HDIM) return;
  int b = i >> 10, hh = i & (HDIM - 1);
  float gi = bih[hh]            + bhh[hh];
  float gf = bih[HDIM + hh]     + bhh[HDIM + hh];
  float gg = bih[2 * HDIM + hh] + bhh[2 * HDIM + hh];
  float go = bih[3 * HDIM + hh] + bhh[3 * HDIM + hh];
#pragma unroll
  for (int s = 0; s < 8; s++) {
    gi += g_part[s][b][hh];
    gf += g_part[s][b][HDIM + hh];
    gg += g_part[s][b][2 * HDIM + hh];
    go += g_part[s][b][3 * HDIM + hh];
  }
  float si = 1.f / (1.f + expf(-gi));
  float sf = 1.f / (1.f + expf(-gf));
  float so = 1.f / (1.f + expf(-go));
  float cn = sf * g_c[layer][b][hh] + si * tanhf(gg);
  float hn = so * tanhf(cn);
  g_c[layer][b][hh] = cn;
  __nv_bfloat16 h0, h1, h2;
  split3(hn, h0, h1, h2);
  d_hs[layer][0][b * HDIM + hh] = h0;
  d_hs[layer][1][b * HDIM + hh] = h1;
  d_hs[layer][2][b * HDIM + hh] = h2;
}

// reduce 8 o2emb partials + bias, ReLU, emit hid limbs
__global__ void k_hidred(const float* __restrict__ o2b) {
  int i = blockIdx.x * blockDim.x + threadIdx.x;
  if (i >= BSZ * EDIM) return;
  int b = i >> 10, e = i & (EDIM - 1);
  float s = o2b[e];
#pragma unroll
  for (int c = 0; c < 8; c++) s += e_part[c][b][e];
  s = fmaxf(s, 0.f);
  __nv_bfloat16 h0, h1, h2;
  split3(s, h0, h1, h2);
  d_hid_s[0][b * EDIM + e] = h0;
  d_hid_s[1][b * EDIM + e] = h1;
  d_hid_s[2][b * EDIM + e] = h2;
}

// final argmax over 500 (block, wn) partials; update tokens, write samples
__global__ void k_argmax(float* __restrict__ out, int t, int write_samples) {
  int tid = threadIdx.x;
  int b = tid >> 2, l4 = tid & 3;
  float bv = -3.0e38f; int bi = 0x7fffffff;
  for (int p = l4; p < 2 * NB_V; p += 4) {
    float v = g_pval[b][p]; int ix = g_pidx[b][p];
    if (v > bv || (v == bv && ix < bi)) { bv = v; bi = ix; }
  }
#pragma unroll
  for (int off = 2; off >= 1; off >>= 1) {
    float ov = __shfl_down_sync(0xffffffffu, bv, off, 4);
    int   oi = __shfl_down_sync(0xffffffffu, bi, off, 4);
    if (ov > bv || (ov == bv && oi < bi)) { bv = ov; bi = oi; }
  }
  if (l4 == 0) {
    g_tok[b] = bi;
    if (write_samples)
      out[(size_t)BSZ * TST * VOCAB + (size_t)b * TST + t] = (float)bi;
  }
}

// ---------------- host orchestration (graph-capturable) ----------------
extern "C" void kernel_launch(void* const* d_in, const int* in_sizes, int n_in,
                              void* d_out, int out_size) {
  const float* emb = (const float*)d_in[0];
  const float* wih = (const float*)d_in[1];
  const float* whh = (const float*)d_in[2];
  const float* bih = (const float*)d_in[3];
  const float* bhh = (const float*)d_in[4];
  const float* o2w = (const float*)d_in[5];
  const float* o2b = (const float*)d_in[6];
  const float* sw  = (const float*)d_in[7];
  const float* sb  = (const float*)d_in[8];
  float* out = (float*)d_out;
  int wsamp = (out_size >= BSZ * TST * VOCAB + BSZ * TST) ? 1 : 0;

  cudaFuncSetAttribute(k_mm, cudaFuncAttributeMaxDynamicSharedMemorySize, SMEM_SZ);

  k_init<<<1024, 256>>>();
  k_splitw<<<1184, 256>>>(wih, 0, (long long)NLAY * GDIM * HDIM);
  k_splitw<<<1184, 256>>>(whh, 1, (long long)NLAY * GDIM * HDIM);
  k_splitw<<<592, 256>>>(o2w, 2, (long long)EDIM * HDIM);
  k_splitw<<<1184, 256>>>(sw, 3, (long long)VOCAB * EDIM);

  for (int t = 0; t < TST; t++) {
    k_embed<<<256, 256>>>(emb);
    // layer 0: x@Wih0 (y<4) + h0@Whh0 (y>=4), 4 K-chunks each
    k_mm<<<dim3(GDIM / 128, 8), 128, SMEM_SZ>>>(0, 0, 1, 1, 4, 4, 0, nullptr, nullptr, 0);
    k_act<<<256, 256>>>(bih, bhh, 0);
    // layer 1: h0@Wih1 + h1@Whh1
    k_mm<<<dim3(GDIM / 128, 8), 128, SMEM_SZ>>>(1, 2, 2, 3, 4, 4, 0, nullptr, nullptr, 0);
    k_act<<<256, 256>>>(bih + GDIM, bhh + GDIM, 1);
    // o2emb: h1 @ o2w, 8 split-K slices of 2 chunks
    k_mm<<<dim3(EDIM / 128, 8), 128, SMEM_SZ>>>(2, 4, 2, 4, 2, 8, 1, nullptr, nullptr, 0);
    k_hidred<<<256, 256>>>(o2b);
    // score: hid @ sw, full K, fused bias/out/argmax
    k_mm<<<dim3(NB_V, 1), 128, SMEM_SZ>>>(3, 5, 3, 5, 16, 1, 2, sb, out, t);
    k_argmax<<<1, 256>>>(out, t, wsamp);
  }
}

// round 13
// speedup vs baseline: 2.7115x; 1.7005x over previous
#include <cuda_runtime.h>
#include <cuda_fp16.h>
#include <cstdint>

#define VOCAB 32000
#define EDIM  1024
#define HDIM  1024
#define NLAY  2
#define BSZ   64
#define TST   64
#define GDIM  4096
#define NPART 250                     /* 125 score blocks x 2 warp-halves */
#define START_TOK 1

#define RS 72                         /* smem row stride in fp16 elems */
#define A_LIMB (64*RS)
#define B_LIMB (256*RS)
#define STAGE_ELE (2*A_LIMB + 2*B_LIMB)      /* 46080 fp16 */
#define SMEM_SZ (2*STAGE_ELE*2)              /* 184320 B, 2 stages */
#define SCL 1024.0f
#define SCI (1.0f/(1024.0f*1024.0f))

// ---------------- device globals (no allocation allowed) -------------------
__device__ __half d_wih_s[2][NLAY*GDIM*HDIM];
__device__ __half d_whh_s[2][NLAY*GDIM*HDIM];
__device__ __half d_o2w_s[2][EDIM*HDIM];
__device__ __half d_sw_s[2][VOCAB*EDIM];
__device__ __half d_xs[2][64*HDIM];
__device__ __half d_hs[NLAY][2][64*HDIM];
__device__ __half d_hid_s[2][64*HDIM];
__device__ float g_part[8][BSZ][GDIM];
__device__ float e_part[8][BSZ][EDIM];
__device__ float g_c[NLAY][BSZ][HDIM];
__device__ float g_pval[BSZ][256];
__device__ int   g_pidx[BSZ][256];
__device__ int   g_tok[BSZ];

// fp16 warp MMA: D(16x8,f32) += A(16x16,row) * B(16x8,col)  [sm_80+, plain]
#define MMA_F16(d, a, b)                                                      \
  asm volatile("mma.sync.aligned.m16n8k16.row.col.f32.f16.f16.f32 "           \
    "{%0,%1,%2,%3},{%4,%5,%6,%7},{%8,%9},{%0,%1,%2,%3};"                      \
    : "+f"((d)[0]), "+f"((d)[1]), "+f"((d)[2]), "+f"((d)[3])                  \
    : "r"((a)[0]), "r"((a)[1]), "r"((a)[2]), "r"((a)[3]),                     \
      "r"((b)[0]), "r"((b)[1]))

#define LDSM_X4(r0,r1,r2,r3, ad)                                              \
  asm volatile("ldmatrix.sync.aligned.m8n8.x4.shared.b16 {%0,%1,%2,%3}, [%4];"\
    : "=r"(r0), "=r"(r1), "=r"(r2), "=r"(r3) : "r"(ad))
#define LDSM_X2(r0,r1, ad)                                                    \
  asm volatile("ldmatrix.sync.aligned.m8n8.x2.shared.b16 {%0,%1}, [%2];"      \
    : "=r"(r0), "=r"(r1) : "r"(ad))

#define CP_A16(dst, src)                                                      \
  asm volatile("cp.async.cg.shared.global [%0], [%1], 16;"                    \
    :: "r"(dst), "l"(src) : "memory")
#define CP_COMMIT() asm volatile("cp.async.commit_group;" ::: "memory")
#define CP_WAIT0()  asm volatile("cp.async.wait_group 0;" ::: "memory")
#define CP_WAIT1()  asm volatile("cp.async.wait_group 1;" ::: "memory")

__device__ __forceinline__ uint32_t smem_u32(const void* p) {
  uint32_t a;
  asm("{ .reg .u64 t; cvta.to.shared.u64 t, %1; cvt.u32.u64 %0, t; }" : "=r"(a) : "l"(p));
  return a;
}
// fp32 -> 2 fp16 limbs, pre-scaled by 2^10 (residual ~2^-22 relative)
__device__ __forceinline__ void split2(float x, __half& h0, __half& h1) {
  float s = x * SCL;
  h0 = __float2half_rn(s);
  h1 = __float2half_rn(s - __half2float(h0));
}
__device__ __forceinline__ const __half* getA(int s, int l) {
  switch (s) { case 0: return d_xs[l]; case 1: return d_hs[0][l];
               case 2: return d_hs[1][l]; default: return d_hid_s[l]; }
}
__device__ __forceinline__ const __half* getB(int s, int l) {
  switch (s) {
    case 0: return d_wih_s[l];
    case 1: return d_whh_s[l];
    case 2: return d_wih_s[l] + (size_t)GDIM * HDIM;
    case 3: return d_whh_s[l] + (size_t)GDIM * HDIM;
    case 4: return d_o2w_s[l];
    default: return d_sw_s[l];
  }
}

// ---------------- setup kernels ----------------
__global__ void k_init() {
  int i = blockIdx.x * blockDim.x + threadIdx.x;
  if (i < 2 * 64 * HDIM)        (&d_xs[0][0])[i]    = __float2half(0.f);
  if (i < NLAY * 2 * 64 * HDIM) (&d_hs[0][0][0])[i] = __float2half(0.f);
  if (i < 2 * 64 * HDIM)        (&d_hid_s[0][0])[i] = __float2half(0.f);
  if (i < NLAY * BSZ * HDIM)    (&g_c[0][0][0])[i]  = 0.f;
  if (i < BSZ) g_tok[i] = START_TOK;
}

__global__ void k_embed0(const float* __restrict__ emb) {
  int i = blockIdx.x * blockDim.x + threadIdx.x;
  if (i >= BSZ * EDIM) return;
  int b = i >> 10, e = i & (EDIM - 1);
  __half h0, h1;
  split2(emb[(size_t)g_tok[b] * EDIM + e], h0, h1);
  d_xs[0][b * HDIM + e] = h0; d_xs[1][b * HDIM + e] = h1;
}

__global__ void k_splitw(const float* __restrict__ src, int which, long long n) {
  __half *p0, *p1;
  switch (which) {
    case 0:  p0 = d_wih_s[0]; p1 = d_wih_s[1]; break;
    case 1:  p0 = d_whh_s[0]; p1 = d_whh_s[1]; break;
    case 2:  p0 = d_o2w_s[0]; p1 = d_o2w_s[1]; break;
    default: p0 = d_sw_s[0];  p1 = d_sw_s[1];  break;
  }
  long long stride = (long long)gridDim.x * blockDim.x;
  for (long long i = (long long)blockIdx.x * blockDim.x + threadIdx.x; i < n; i += stride) {
    __half h0, h1;
    split2(src[i], h0, h1);
    p0[i] = h0; p1[i] = h1;
  }
}

// ---------------- fp16x2 HMMA GEMM, 256 thr, M64 x N256, 2-stage cp.async --
// 8 warps: wm=wid&3 (M16 slice), wn=wid>>2 (N128 half).
// mode 0: gates partial -> g_part[y]; 1: o2emb partial -> e_part[y];
// mode 2: score fused bias + out store + per-(block,wn) argmax partial.
__global__ __launch_bounds__(256) void k_mm(int a1, int b1, int a2, int b2,
                                            int cpb, int ysplit, int mode,
                                            const float* __restrict__ bias,
                                            float* __restrict__ out, int t) {
  extern __shared__ __half sm[];
  const uint32_t sbase = smem_u32(sm);
  const int tid = threadIdx.x, wid = tid >> 5, lane = tid & 31;
  const int qr = lane >> 2, qc = lane & 3;
  const int wm = wid & 3, wn = wid >> 2;
  const int n0 = blockIdx.x * 256;
  const int y = blockIdx.y;
  const int as = (y < ysplit) ? a1 : a2, bs = (y < ysplit) ? b1 : b2;
  const int kbase = ((y < ysplit) ? y : (y - ysplit)) * cpb * 64;

  const __half* Ap[2]; const __half* Bp[2];
#pragma unroll
  for (int l = 0; l < 2; l++) { Ap[l] = getA(as, l); Bp[l] = getB(bs, l); }

  // ldmatrix per-lane address pieces (same recipe as validated R8 kernel)
  const int arow = ((lane >> 3) & 1) * 8 + (lane & 7);
  const int akof = ((lane >> 4) & 1) * 8;
  const uint32_t A_pre = (uint32_t)(((wm * 16 + arow) * RS + akof) * 2);
  const int brow = lane & 7;
  const int bkof = ((lane >> 3) & 1) * 8;
  const uint32_t B_pre = (uint32_t)(((wn * 128 + brow) * RS + bkof) * 2);

  float acc[16][4];
#pragma unroll
  for (int i = 0; i < 16; i++)
#pragma unroll
    for (int j = 0; j < 4; j++) acc[i][j] = 0.f;

  auto issue_load = [&](int s, int ch) {
    const int kpos = kbase + ch * 64;
    const uint32_t st = sbase + (uint32_t)(s * STAGE_ELE * 2);
#pragma unroll 2
    for (int i = tid; i < 2 * 512; i += 256) {      // A: 2 limbs x 64r x 64k
      int l = i >> 9, q = i & 511, row = q >> 3, f8 = q & 7;
      CP_A16(st + (uint32_t)((l * A_LIMB + row * RS + f8 * 8) * 2),
             Ap[l] + (size_t)row * 1024 + kpos + f8 * 8);
    }
#pragma unroll 4
    for (int i = tid; i < 2 * 2048; i += 256) {     // B: 2 limbs x 256r x 64k
      int l = i >> 11, q = i & 2047, row = q >> 3, f8 = q & 7;
      CP_A16(st + (uint32_t)((2 * A_LIMB + l * B_LIMB + row * RS + f8 * 8) * 2),
             Bp[l] + (size_t)(n0 + row) * 1024 + kpos + f8 * 8);
    }
    CP_COMMIT();
  };

  issue_load(0, 0);

  for (int ch = 0; ch < cpb; ch++) {
    const int cur = ch & 1;
    if (ch + 1 < cpb) { issue_load(cur ^ 1, ch + 1); CP_WAIT1(); }
    else              { CP_WAIT0(); }
    __syncthreads();
    const uint32_t sA = sbase + (uint32_t)(cur * STAGE_ELE * 2);
    const uint32_t sB = sA + (uint32_t)(2 * A_LIMB * 2);

#pragma unroll
    for (int k16 = 0; k16 < 4; k16++) {
      uint32_t afr[2][4];
      const uint32_t ak = sA + A_pre + k16 * 32;
#pragma unroll
      for (int l = 0; l < 2; l++)
        LDSM_X4(afr[l][0], afr[l][1], afr[l][2], afr[l][3],
                ak + (uint32_t)(l * A_LIMB * 2));
      const uint32_t bk = sB + B_pre + k16 * 32;
#pragma unroll
      for (int n8 = 0; n8 < 16; n8++) {
        uint32_t bfr[2][2];
#pragma unroll
        for (int l = 0; l < 2; l++)
          LDSM_X2(bfr[l][0], bfr[l][1],
                  bk + (uint32_t)((l * B_LIMB + n8 * 8 * RS) * 2));
        MMA_F16(acc[n8], afr[0], bfr[0]);   // a0*b0
        MMA_F16(acc[n8], afr[0], bfr[1]);   // a0*b1
        MMA_F16(acc[n8], afr[1], bfr[0]);   // a1*b0
      }
    }
    __syncthreads();
  }

  // epilogue: rows r0=wm*16+qr, r1=r0+8; cols n0+wn*128+n8*8+qc*2 (+1)
  const int r0 = wm * 16 + qr, r1 = r0 + 8;
  if (mode == 2) {
    float bv0 = -3.0e38f, bv1 = -3.0e38f; int bi0 = 0, bi1 = 0;
#pragma unroll
    for (int n8 = 0; n8 < 16; n8++) {
      int c = n0 + wn * 128 + n8 * 8 + qc * 2;
      float b0 = bias[c], b1 = bias[c + 1];
      float v00 = acc[n8][0] * SCI + b0, v01 = acc[n8][1] * SCI + b1;
      float v10 = acc[n8][2] * SCI + b0, v11 = acc[n8][3] * SCI + b1;
      *(float2*)(out + ((size_t)r0 * TST + t) * VOCAB + c) = make_float2(v00, v01);
      *(float2*)(out + ((size_t)r1 * TST + t) * VOCAB + c) = make_float2(v10, v11);
      if (v00 > bv0) { bv0 = v00; bi0 = c; }
      if (v01 > bv0) { bv0 = v01; bi0 = c + 1; }
      if (v10 > bv1) { bv1 = v10; bi1 = c; }
      if (v11 > bv1) { bv1 = v11; bi1 = c + 1; }
    }
#pragma unroll
    for (int m = 1; m <= 2; m <<= 1) {      // reduce over qc quad
      float ov = __shfl_xor_sync(0xffffffffu, bv0, m);
      int   oi = __shfl_xor_sync(0xffffffffu, bi0, m);
      if (ov > bv0 || (ov == bv0 && oi < bi0)) { bv0 = ov; bi0 = oi; }
      ov = __shfl_xor_sync(0xffffffffu, bv1, m);
      oi = __shfl_xor_sync(0xffffffffu, bi1, m);
      if (ov > bv1 || (ov == bv1 && oi < bi1)) { bv1 = ov; bi1 = oi; }
    }
    if (qc == 0) {
      g_pval[r0][blockIdx.x * 2 + wn] = bv0; g_pidx[r0][blockIdx.x * 2 + wn] = bi0;
      g_pval[r1][blockIdx.x * 2 + wn] = bv1; g_pidx[r1][blockIdx.x * 2 + wn] = bi1;
    }
  } else {
    float* base = (mode == 0) ? &g_part[y][0][0] : &e_part[y][0][0];
    const int ld = (mode == 0) ? GDIM : EDIM;
#pragma unroll
    for (int n8 = 0; n8 < 16; n8++) {
      int c = n0 + wn * 128 + n8 * 8 + qc * 2;
      *(float2*)(base + (size_t)r0 * ld + c) =
          make_float2(acc[n8][0] * SCI, acc[n8][1] * SCI);
      *(float2*)(base + (size_t)r1 * ld + c) =
          make_float2(acc[n8][2] * SCI, acc[n8][3] * SCI);
    }
  }
}

// reduce 8 gate partials + biases, LSTM cell, emit h limbs + c
__global__ void k_act(const float* __restrict__ bih, const float* __restrict__ bhh,
                      int layer) {
  int i = blockIdx.x * blockDim.x + threadIdx.x;
  if (i >= BSZ * HDIM) return;
  int b = i >> 10, hh = i & (HDIM - 1);
  float gi = bih[hh]            + bhh[hh];
  float gf = bih[HDIM + hh]     + bhh[HDIM + hh];
  float gg = bih[2 * HDIM + hh] + bhh[2 * HDIM + hh];
  float go = bih[3 * HDIM + hh] + bhh[3 * HDIM + hh];
#pragma unroll
  for (int s = 0; s < 8; s++) {
    gi += g_part[s][b][hh];
    gf += g_part[s][b][HDIM + hh];
    gg += g_part[s][b][2 * HDIM + hh];
    go += g_part[s][b][3 * HDIM + hh];
  }
  float si = 1.f / (1.f + expf(-gi));
  float sf = 1.f / (1.f + expf(-gf));
  float so = 1.f / (1.f + expf(-go));
  float cn = sf * g_c[layer][b][hh] + si * tanhf(gg);
  float hn = so * tanhf(cn);
  g_c[layer][b][hh] = cn;
  __half h0, h1;
  split2(hn, h0, h1);
  d_hs[layer][0][b * HDIM + hh] = h0;
  d_hs[layer][1][b * HDIM + hh] = h1;
}

// reduce 8 o2emb partials + bias, ReLU, emit hid limbs
__global__ void k_hidred(const float* __restrict__ o2b) {
  int i = blockIdx.x * blockDim.x + threadIdx.x;
  if (i >= BSZ * EDIM) return;
  int b = i >> 10, e = i & (EDIM - 1);
  float s = o2b[e];
#pragma unroll
  for (int c = 0; c < 8; c++) s += e_part[c][b][e];
  s = fmaxf(s, 0.f);
  __half h0, h1;
  split2(s, h0, h1);
  d_hid_s[0][b * EDIM + e] = h0;
  d_hid_s[1][b * EDIM + e] = h1;
}

// fused: final argmax over 250 partials for row b, then embed+split next token
__global__ __launch_bounds__(256) void k_argemb(const float* __restrict__ emb,
                                                float* __restrict__ out,
                                                int t, int wsamp) {
  __shared__ float sv[256];
  __shared__ int   si[256];
  __shared__ int   stok;
  const int b = blockIdx.x, tid = threadIdx.x;
  float bv = -3.0e38f; int bi = 0x7fffffff;
  if (tid < NPART) { bv = g_pval[b][tid]; bi = g_pidx[b][tid]; }
  sv[tid] = bv; si[tid] = bi;
  __syncthreads();
  for (int s = 128; s > 0; s >>= 1) {
    if (tid < s) {
      float v = sv[tid + s]; int ix = si[tid + s];
      if (v > sv[tid] || (v == sv[tid] && ix < si[tid])) { sv[tid] = v; si[tid] = ix; }
    }
    __syncthreads();
  }
  if (tid == 0) {
    stok = si[0];
    g_tok[b] = si[0];
    if (wsamp)
      out[(size_t)BSZ * TST * VOCAB + (size_t)b * TST + t] = (float)si[0];
  }
  __syncthreads();
  const int tok = stok;
  for (int e = tid; e < EDIM; e += 256) {
    __half h0, h1;
    split2(emb[(size_t)tok * EDIM + e], h0, h1);
    d_xs[0][b * HDIM + e] = h0;
    d_xs[1][b * HDIM + e] = h1;
  }
}

// ---------------- host orchestration (graph-capturable) ----------------
extern "C" void kernel_launch(void* const* d_in, const int* in_sizes, int n_in,
                              void* d_out, int out_size) {
  const float* emb = (const float*)d_in[0];
  const float* wih = (const float*)d_in[1];
  const float* whh = (const float*)d_in[2];
  const float* bih = (const float*)d_in[3];
  const float* bhh = (const float*)d_in[4];
  const float* o2w = (const float*)d_in[5];
  const float* o2b = (const float*)d_in[6];
  const float* sw  = (const float*)d_in[7];
  const float* sb  = (const float*)d_in[8];
  float* out = (float*)d_out;
  int wsamp = (out_size >= BSZ * TST * VOCAB + BSZ * TST) ? 1 : 0;

  cudaFuncSetAttribute(k_mm, cudaFuncAttributeMaxDynamicSharedMemorySize, SMEM_SZ);

  // launch order puts the first gates k_mm at index 5 so ncu (-s 5 -c 1)
  // finally captures the GEMM engine instead of k_splitw.
  k_init<<<1024, 256>>>();                                            // 0
  k_embed0<<<256, 256>>>(emb);                                        // 1
  k_splitw<<<1184, 256>>>(wih, 0, (long long)NLAY * GDIM * HDIM);     // 2
  k_splitw<<<1184, 256>>>(whh, 1, (long long)NLAY * GDIM * HDIM);     // 3
  k_splitw<<<592, 256>>>(o2w, 2, (long long)EDIM * HDIM);             // 4

  for (int t = 0; t < TST; t++) {
    // layer 0: x@Wih0 (y<4) + h0@Whh0 (y>=4), 4 K-chunks per slice
    k_mm<<<dim3(GDIM / 256, 8), 256, SMEM_SZ>>>(0, 0, 1, 1, 4, 4, 0, nullptr, nullptr, 0);
    if (t == 0)   // score weights only needed below; split after first gates
      k_splitw<<<1184, 256>>>(sw, 3, (long long)VOCAB * EDIM);
    k_act<<<256, 256>>>(bih, bhh, 0);
    // layer 1: h0@Wih1 + h1@Whh1
    k_mm<<<dim3(GDIM / 256, 8), 256, SMEM_SZ>>>(1, 2, 2, 3, 4, 4, 0, nullptr, nullptr, 0);
    k_act<<<256, 256>>>(bih + GDIM, bhh + GDIM, 1);
    // o2emb: h1 @ o2w, 8 split-K slices of 2 chunks
    k_mm<<<dim3(EDIM / 256, 8), 256, SMEM_SZ>>>(2, 4, 2, 4, 2, 8, 1, nullptr, nullptr, 0);
    k_hidred<<<256, 256>>>(o2b);
    // score: hid @ sw, full K, fused bias/out/argmax partials
    k_mm<<<dim3(VOCAB / 256, 1), 256, SMEM_SZ>>>(3, 5, 3, 5, 16, 1, 2, sb, out, t);
    // fused final argmax + next-token embed/split
    k_argemb<<<BSZ, 256>>>(emb, out, t, wsamp);
  }
}